// round 1
// baseline (speedup 1.0000x reference)
#include <cuda_runtime.h>
#include <cstdint>

#define NEG_INF __int_as_float(0xff800000)

static __device__ __forceinline__ float max5(float a, float b, float c, float d, float e) {
    return fmaxf(fmaxf(a, fmaxf(b, c)), fmaxf(d, e));
}

// Hex maxpool, SIZE=2, STRIDE=1, plane = 256x256 fp32.
// out[h][w] = max over hex window:
//   even w: col w rows [h-2,h+2]; cols w+-1 rows [h-2,h+1]; cols w+-2 rows [h-1,h+1]
//   odd  w: col w rows [h-2,h+2]; cols w+-1 rows [h-1,h+2]; cols w+-2 rows [h-1,h+1]
//
// One warp handles a full 256-wide row strip of 64 rows. Lane owns 8 columns.
// Rolling 5-row register window (mod-5 slots), per-column vertical maxes
// (m3 / A / m5), horizontal halo via 6 warp shuffles per row.
__global__ __launch_bounds__(256, 2)
void hexpool_kernel(const float* __restrict__ x, float* __restrict__ y) {
    const int warp_global = blockIdx.x * 8 + (threadIdx.x >> 5);
    const int lane  = threadIdx.x & 31;
    const int img   = warp_global >> 2;   // 1024 planes (N*C)
    const int chunk = warp_global & 3;    // 4 chunks of 64 rows
    const int h0    = chunk * 64;

    const float* __restrict__ in  = x + (size_t)img * 65536 + lane * 8;
    float*       __restrict__ out = y + (size_t)img * 65536 + lane * 8;

    float win[5][8];

    auto load_row = [&](int g, float* dst) {
        if ((unsigned)g < 256u) {
            const float4 a = *reinterpret_cast<const float4*>(in + g * 256);
            const float4 b = *reinterpret_cast<const float4*>(in + g * 256 + 4);
            dst[0] = a.x; dst[1] = a.y; dst[2] = a.z; dst[3] = a.w;
            dst[4] = b.x; dst[5] = b.y; dst[6] = b.z; dst[7] = b.w;
        } else {
            #pragma unroll
            for (int j = 0; j < 8; ++j) dst[j] = NEG_INF;
        }
    };

    // Prologue: local rows m = -2..2 live in slot (m mod 5) = 3,4,0,1,2
    load_row(h0 - 2, win[3]);
    load_row(h0 - 1, win[4]);
    load_row(h0 + 0, win[0]);
    load_row(h0 + 1, win[1]);
    load_row(h0 + 2, win[2]);

    for (int hh = 0; hh < 64; hh += 5) {
        #pragma unroll
        for (int u = 0; u < 5; ++u) {
            const int l = hh + u;
            if (l < 64) {
                // slot of local row (l+k) is (u+k) mod 5 since hh % 5 == 0
                const int s0 = (u + 3) % 5;  // row l-2
                const int s1 = (u + 4) % 5;  // row l-1
                const int sc =  u;           // row l
                const int s3 = (u + 1) % 5;  // row l+1
                const int s4 = (u + 2) % 5;  // row l+2

                float m3[8], A[8], m5v[8];
                #pragma unroll
                for (int j = 0; j < 8; ++j)
                    m3[j] = fmaxf(fmaxf(win[s1][j], win[sc][j]), win[s3][j]);

                // column parity: global col = lane*8 + j, so parity == j&1.
                // A[w] = the 4-row max that w's *neighbors* read:
                //   odd  w -> rows [h-2,h+1] = max(m3, r0)
                //   even w -> rows [h-1,h+2] = max(m3, r4)
                // m5[w] = 5-row max = max(A, remaining row)
                #pragma unroll
                for (int j = 0; j < 8; ++j) {
                    if (j & 1) { A[j]  = fmaxf(m3[j], win[s0][j]);
                                 m5v[j] = fmaxf(A[j], win[s4][j]); }
                    else       { A[j]  = fmaxf(m3[j], win[s4][j]);
                                 m5v[j] = fmaxf(A[j], win[s0][j]); }
                }

                // Horizontal halo across lanes
                float A_l   = __shfl_up_sync(0xffffffffu, A[7], 1);
                float m3_l2 = __shfl_up_sync(0xffffffffu, m3[6], 1);
                float m3_l1 = __shfl_up_sync(0xffffffffu, m3[7], 1);
                float A_r   = __shfl_down_sync(0xffffffffu, A[0], 1);
                float m3_r1 = __shfl_down_sync(0xffffffffu, m3[0], 1);
                float m3_r2 = __shfl_down_sync(0xffffffffu, m3[1], 1);
                if (lane == 0)  { A_l = NEG_INF; m3_l1 = NEG_INF; m3_l2 = NEG_INF; }
                if (lane == 31) { A_r = NEG_INF; m3_r1 = NEG_INF; m3_r2 = NEG_INF; }

                float4 v0, v1;
                v0.x = max5(m5v[0], A_l,  A[1], m3_l2, m3[2]);
                v0.y = max5(m5v[1], A[0], A[2], m3_l1, m3[3]);
                v0.z = max5(m5v[2], A[1], A[3], m3[0], m3[4]);
                v0.w = max5(m5v[3], A[2], A[4], m3[1], m3[5]);
                v1.x = max5(m5v[4], A[3], A[5], m3[2], m3[6]);
                v1.y = max5(m5v[5], A[4], A[6], m3[3], m3[7]);
                v1.z = max5(m5v[6], A[5], A[7], m3[4], m3_r1);
                v1.w = max5(m5v[7], A[6], A_r,  m3[5], m3_r2);

                *reinterpret_cast<float4*>(out + (h0 + l) * 256)     = v0;
                *reinterpret_cast<float4*>(out + (h0 + l) * 256 + 4) = v1;

                // Prefetch row l+3 into the slot that held row l-2 (now dead).
                // Its first consumer is late in the NEXT iteration -> latency slack.
                if (l < 63) load_row(h0 + l + 3, win[s0]);
            }
        }
    }
}

extern "C" void kernel_launch(void* const* d_in, const int* in_sizes, int n_in,
                              void* d_out, int out_size) {
    const float* x = (const float*)d_in[0];
    float*       y = (float*)d_out;
    // 1024 planes * 4 chunks = 4096 warps; 8 warps/block -> 512 blocks
    hexpool_kernel<<<512, 256>>>(x, y);
}

// round 2
// speedup vs baseline: 1.2060x; 1.2060x over previous
#include <cuda_runtime.h>
#include <cstdint>

#define NEG_INF __int_as_float(0xff800000)

static __device__ __forceinline__ float max5(float a, float b, float c, float d, float e) {
    return fmaxf(fmaxf(a, fmaxf(b, c)), fmaxf(d, e));
}

// Hex maxpool, SIZE=2, STRIDE=1, plane = 256x256 fp32.
// out[h][w] = max over hex window:
//   even w: col w rows [h-2,h+2]; cols w+-1 rows [h-2,h+1]; cols w+-2 rows [h-1,h+1]
//   odd  w: col w rows [h-2,h+2]; cols w+-1 rows [h-1,h+2]; cols w+-2 rows [h-1,h+1]
//
// One warp per 256-wide strip of 64 rows; lane owns 8 columns (2x float4 per row).
// 8-slot rolling register window (power-of-2 => compile-time slots with 8x unroll),
// prefetch distance +4 rows => each LDG consumed TWO iterations after issue
// => ~4 LDG.128 in flight per warp (vs 2 in R1) to cover DRAM latency.
__global__ __launch_bounds__(256, 2)
void hexpool_kernel(const float* __restrict__ x, float* __restrict__ y) {
    const int warp_global = blockIdx.x * 8 + (threadIdx.x >> 5);
    const int lane  = threadIdx.x & 31;
    const int img   = warp_global >> 2;   // 1024 planes (N*C)
    const int chunk = warp_global & 3;    // 4 chunks of 64 rows
    const int h0    = chunk * 64;

    const float* __restrict__ in  = x + (size_t)img * 65536 + lane * 8;
    float*       __restrict__ out = y + (size_t)img * 65536 + lane * 8;

    // slot for local row m is (m+2) & 7
    float win[8][8];

    auto load_row = [&](int m, float* dst) {
        const int g = h0 + m;
        if ((unsigned)g < 256u) {
            const float4 a = *reinterpret_cast<const float4*>(in + g * 256);
            const float4 b = *reinterpret_cast<const float4*>(in + g * 256 + 4);
            dst[0] = a.x; dst[1] = a.y; dst[2] = a.z; dst[3] = a.w;
            dst[4] = b.x; dst[5] = b.y; dst[6] = b.z; dst[7] = b.w;
        } else {
            #pragma unroll
            for (int j = 0; j < 8; ++j) dst[j] = NEG_INF;
        }
    };

    // Prologue: local rows -2..3 -> slots 0..5
    #pragma unroll
    for (int m = -2; m <= 3; ++m) load_row(m, win[(m + 2) & 7]);

    for (int hh = 0; hh < 64; hh += 8) {
        #pragma unroll
        for (int u = 0; u < 8; ++u) {
            const int l  = hh + u;
            // hh % 8 == 0, so slot of row (l+k) = (u + k + 2) & 7 (compile-time)
            const int s0 = (u + 0) & 7;  // row l-2
            const int s1 = (u + 1) & 7;  // row l-1
            const int sc = (u + 2) & 7;  // row l
            const int s3 = (u + 3) & 7;  // row l+1
            const int s4 = (u + 4) & 7;  // row l+2
            const int sp = (u + 6) & 7;  // target slot for prefetched row l+4

            float m3[8], A[8], m5v[8];
            #pragma unroll
            for (int j = 0; j < 8; ++j)
                m3[j] = fmaxf(fmaxf(win[s1][j], win[sc][j]), win[s3][j]);

            // column parity: global col = lane*8 + j, parity == j&1.
            // A[w] = the 4-row max that w's *neighbors* read:
            //   odd  w -> rows [h-2,h+1] = max(m3, r_{l-2})
            //   even w -> rows [h-1,h+2] = max(m3, r_{l+2})
            // m5[w] = full 5-row max = max(A, remaining row)
            #pragma unroll
            for (int j = 0; j < 8; ++j) {
                if (j & 1) { A[j]   = fmaxf(m3[j], win[s0][j]);
                             m5v[j] = fmaxf(A[j], win[s4][j]); }
                else       { A[j]   = fmaxf(m3[j], win[s4][j]);
                             m5v[j] = fmaxf(A[j], win[s0][j]); }
            }

            // Horizontal halo across lanes
            float A_l   = __shfl_up_sync(0xffffffffu, A[7], 1);
            float m3_l2 = __shfl_up_sync(0xffffffffu, m3[6], 1);
            float m3_l1 = __shfl_up_sync(0xffffffffu, m3[7], 1);
            float A_r   = __shfl_down_sync(0xffffffffu, A[0], 1);
            float m3_r1 = __shfl_down_sync(0xffffffffu, m3[0], 1);
            float m3_r2 = __shfl_down_sync(0xffffffffu, m3[1], 1);
            if (lane == 0)  { A_l = NEG_INF; m3_l1 = NEG_INF; m3_l2 = NEG_INF; }
            if (lane == 31) { A_r = NEG_INF; m3_r1 = NEG_INF; m3_r2 = NEG_INF; }

            float4 v0, v1;
            v0.x = max5(m5v[0], A_l,  A[1], m3_l2, m3[2]);
            v0.y = max5(m5v[1], A[0], A[2], m3_l1, m3[3]);
            v0.z = max5(m5v[2], A[1], A[3], m3[0], m3[4]);
            v0.w = max5(m5v[3], A[2], A[4], m3[1], m3[5]);
            v1.x = max5(m5v[4], A[3], A[5], m3[2], m3[6]);
            v1.y = max5(m5v[5], A[4], A[6], m3[3], m3[7]);
            v1.z = max5(m5v[6], A[5], A[7], m3[4], m3_r1);
            v1.w = max5(m5v[7], A[6], A_r,  m3[5], m3_r2);

            // Output never re-read: evict-first stores keep L2 for the row halo.
            __stcs(reinterpret_cast<float4*>(out + (h0 + l) * 256),     v0);
            __stcs(reinterpret_cast<float4*>(out + (h0 + l) * 256 + 4), v1);

            // Prefetch row l+4 into slot (u+6)&7 (held row l-4, dead since iter l-2).
            // First consumer is iteration l+2 -> two iterations of latency slack.
            if (l < 62) load_row(l + 4, win[sp]);
        }
    }
}

extern "C" void kernel_launch(void* const* d_in, const int* in_sizes, int n_in,
                              void* d_out, int out_size) {
    const float* x = (const float*)d_in[0];
    float*       y = (float*)d_out;
    // 1024 planes * 4 chunks = 4096 warps; 8 warps/block -> 512 blocks
    hexpool_kernel<<<512, 256>>>(x, y);
}

// round 3
// speedup vs baseline: 1.2421x; 1.0300x over previous
#include <cuda_runtime.h>
#include <cstdint>

#define NEG_INF __int_as_float(0xff800000)

static __device__ __forceinline__ float max5(float a, float b, float c, float d, float e) {
    return fmaxf(fmaxf(a, fmaxf(b, c)), fmaxf(d, e));
}

// Hex maxpool, SIZE=2, STRIDE=1, plane = 256x256 fp32.
//   even w: col w rows [h-2,h+2]; cols w+-1 rows [h-2,h+1]; cols w+-2 rows [h-1,h+1]
//   odd  w: col w rows [h-2,h+2]; cols w+-1 rows [h-1,h+2]; cols w+-2 rows [h-1,h+1]
//
// One warp per 256-wide strip of 64 rows; lane owns 8 columns.
// DRAM latency hidden by a per-warp cp.async (LDGSTS) pipeline into a 6-row
// smem ring (5 rows = 5KB in flight per warp, 80KB/SM — register-free MLP).
// Register window holds rows l-2..l+2 plus the row being LDS'd (8 slots for
// compile-time indexing, only 6 live).
__global__ __launch_bounds__(256, 2)
void hexpool_kernel(const float* __restrict__ x, float* __restrict__ y) {
    __shared__ float ring[8][6][256];   // 48KB: warp-private 6-row rings

    const int wid  = threadIdx.x >> 5;
    const int lane = threadIdx.x & 31;
    const int warp_global = blockIdx.x * 8 + wid;
    const int img   = warp_global >> 2;   // 1024 planes (N*C)
    const int chunk = warp_global & 3;    // 4 chunks of 64 rows
    const int h0    = chunk * 64;

    const float* __restrict__ in  = x + (size_t)img * 65536 + lane * 8;
    float*       __restrict__ out = y + (size_t)img * 65536 + lane * 8;
    float* wring = &ring[wid][0][0];

    // slot for local row m is (m+2) & 7
    float win[8][8];

    // Direct LDG for the prologue window rows (-2..2)
    auto load_row_g = [&](int m, float* dst) {
        const int g = h0 + m;
        if ((unsigned)g < 256u) {
            const float4 a = *reinterpret_cast<const float4*>(in + g * 256);
            const float4 b = *reinterpret_cast<const float4*>(in + g * 256 + 4);
            dst[0] = a.x; dst[1] = a.y; dst[2] = a.z; dst[3] = a.w;
            dst[4] = b.x; dst[5] = b.y; dst[6] = b.z; dst[7] = b.w;
        } else {
            #pragma unroll
            for (int j = 0; j < 8; ++j) dst[j] = NEG_INF;
        }
    };

    // Prefetch local row r into ring slot r%6. ALWAYS commits exactly one
    // group (possibly empty) so wait_group counting stays uniform.
    auto prefetch = [&](int r) {
        if (r <= 65) {
            float* s = wring + (r % 6) * 256 + lane * 8;
            const int g = h0 + r;
            if ((unsigned)g < 256u) {
                const float* gp = in + (size_t)g * 256;
                uint32_t sa = (uint32_t)__cvta_generic_to_shared(s);
                asm volatile(
                    "cp.async.cg.shared.global [%0], [%1], 16;\n\t"
                    "cp.async.cg.shared.global [%2], [%3], 16;\n\t"
                    :: "r"(sa), "l"(gp), "r"(sa + 16), "l"(gp + 4));
            } else {
                const float4 ninf = make_float4(NEG_INF, NEG_INF, NEG_INF, NEG_INF);
                *reinterpret_cast<float4*>(s)     = ninf;
                *reinterpret_cast<float4*>(s + 4) = ninf;
            }
        }
        asm volatile("cp.async.commit_group;");
    };

    auto lds_row = [&](int r, float* dst) {
        const float* s = wring + (r % 6) * 256 + lane * 8;
        const float4 a = *reinterpret_cast<const float4*>(s);
        const float4 b = *reinterpret_cast<const float4*>(s + 4);
        dst[0] = a.x; dst[1] = a.y; dst[2] = a.z; dst[3] = a.w;
        dst[4] = b.x; dst[5] = b.y; dst[6] = b.z; dst[7] = b.w;
    };

    // Prologue: rows -2..2 to registers, rows 3..7 launched into the ring.
    #pragma unroll
    for (int m = -2; m <= 2; ++m) load_row_g(m, win[(m + 2) & 7]);
    #pragma unroll
    for (int r = 3; r <= 7; ++r) prefetch(r);

    for (int hh = 0; hh < 64; hh += 8) {
        #pragma unroll
        for (int u = 0; u < 8; ++u) {
            const int l = hh + u;

            // Keep the async pipe 5 rows deep, then pull row l+3 into regs
            // (consumed next iteration -> full compute body hides the LDS).
            prefetch(l + 8);
            asm volatile("cp.async.wait_group 5;");
            if (l < 63) lds_row(l + 3, win[(u + 5) & 7]);

            // hh % 8 == 0, so slot of row (l+k) = (u + k + 2) & 7 (compile-time)
            const int s0 = (u + 0) & 7;  // row l-2
            const int s1 = (u + 1) & 7;  // row l-1
            const int sc = (u + 2) & 7;  // row l
            const int s3 = (u + 3) & 7;  // row l+1
            const int s4 = (u + 4) & 7;  // row l+2

            float m3[8], A[8], m5v[8];
            #pragma unroll
            for (int j = 0; j < 8; ++j)
                m3[j] = fmaxf(fmaxf(win[s1][j], win[sc][j]), win[s3][j]);

            // parity of global col = j&1.
            //   odd  w: A = rows [h-2,h+1] = max(m3, r_{l-2})
            //   even w: A = rows [h-1,h+2] = max(m3, r_{l+2})
            //   m5 = 5-row max = max(A, remaining row)
            #pragma unroll
            for (int j = 0; j < 8; ++j) {
                if (j & 1) { A[j]   = fmaxf(m3[j], win[s0][j]);
                             m5v[j] = fmaxf(A[j], win[s4][j]); }
                else       { A[j]   = fmaxf(m3[j], win[s4][j]);
                             m5v[j] = fmaxf(A[j], win[s0][j]); }
            }

            // Horizontal halo across lanes
            float A_l   = __shfl_up_sync(0xffffffffu, A[7], 1);
            float m3_l2 = __shfl_up_sync(0xffffffffu, m3[6], 1);
            float m3_l1 = __shfl_up_sync(0xffffffffu, m3[7], 1);
            float A_r   = __shfl_down_sync(0xffffffffu, A[0], 1);
            float m3_r1 = __shfl_down_sync(0xffffffffu, m3[0], 1);
            float m3_r2 = __shfl_down_sync(0xffffffffu, m3[1], 1);
            if (lane == 0)  { A_l = NEG_INF; m3_l1 = NEG_INF; m3_l2 = NEG_INF; }
            if (lane == 31) { A_r = NEG_INF; m3_r1 = NEG_INF; m3_r2 = NEG_INF; }

            float4 v0, v1;
            v0.x = max5(m5v[0], A_l,  A[1], m3_l2, m3[2]);
            v0.y = max5(m5v[1], A[0], A[2], m3_l1, m3[3]);
            v0.z = max5(m5v[2], A[1], A[3], m3[0], m3[4]);
            v0.w = max5(m5v[3], A[2], A[4], m3[1], m3[5]);
            v1.x = max5(m5v[4], A[3], A[5], m3[2], m3[6]);
            v1.y = max5(m5v[5], A[4], A[6], m3[3], m3[7]);
            v1.z = max5(m5v[6], A[5], A[7], m3[4], m3_r1);
            v1.w = max5(m5v[7], A[6], A_r,  m3[5], m3_r2);

            // Output never re-read: evict-first keeps L2 for the row halo.
            __stcs(reinterpret_cast<float4*>(out + (h0 + l) * 256),     v0);
            __stcs(reinterpret_cast<float4*>(out + (h0 + l) * 256 + 4), v1);
        }
    }
}

extern "C" void kernel_launch(void* const* d_in, const int* in_sizes, int n_in,
                              void* d_out, int out_size) {
    const float* x = (const float*)d_in[0];
    float*       y = (float*)d_out;
    // 1024 planes * 4 chunks = 4096 warps; 8 warps/block -> 512 blocks
    hexpool_kernel<<<512, 256>>>(x, y);
}